// round 8
// baseline (speedup 1.0000x reference)
#include <cuda_runtime.h>
#include <cuda_bf16.h>
#include <cstdint>

#define BB   256
#define TT   512
#define II   300
#define HH   64
#define G3   192
#define KP   320      // K padded: 5 chunks of 64
#define NTOT 384      // 192 fwd gates | 192 bwd gates
#define MTOT (BB * TT)
#define RING_D 8      // gru xp prefetch depth (steps)

typedef unsigned long long ull;
typedef uint32_t u32;

__device__ float g_xp[2ull * TT * BB * G3];          // 201 MB scratch
__device__ float g_feat[BB * 256];
__device__ __nv_bfloat16 g_Whi[NTOT * KP];
__device__ __nv_bfloat16 g_Wlo[NTOT * KP];

// ---------------------------------------------------------------------------
// Helpers (plain sm_80+ features — valid on compute_103)
// ---------------------------------------------------------------------------
__device__ __forceinline__ u32 smem_u32(const void* p) {
    u32 a;
    asm("{ .reg .u64 t; cvta.to.shared.u64 t, %1; cvt.u32.u64 %0, t; }" : "=r"(a) : "l"(p));
    return a;
}
__device__ __forceinline__ void cp16(u32 dst, const void* src) {
    asm volatile("cp.async.cg.shared.global [%0], [%1], 16;" :: "r"(dst), "l"(src));
}
// zero-fill variant: src_size=0 -> 16B of zeros, no global read
__device__ __forceinline__ void cp16z(u32 dst, const void* src, bool valid) {
    int sz = valid ? 16 : 0;
    asm volatile("cp.async.cg.shared.global [%0], [%1], 16, %2;"
                 :: "r"(dst), "l"(src), "r"(sz));
}
#define CP_COMMIT()  asm volatile("cp.async.commit_group;" ::: "memory")
#define CP_WAIT(n)   asm volatile("cp.async.wait_group %0;" :: "n"(n) : "memory")

__device__ __forceinline__ void ldm4(u32* r, u32 addr) {
    asm volatile("ldmatrix.sync.aligned.m8n8.x4.shared.b16 {%0,%1,%2,%3}, [%4];"
                 : "=r"(r[0]), "=r"(r[1]), "=r"(r[2]), "=r"(r[3]) : "r"(addr));
}
__device__ __forceinline__ void mma_bf16(float* c, const u32* a, u32 b0, u32 b1) {
    asm volatile("mma.sync.aligned.m16n8k16.row.col.f32.bf16.bf16.f32 "
                 "{%0,%1,%2,%3}, {%4,%5,%6,%7}, {%8,%9}, {%0,%1,%2,%3};"
                 : "+f"(c[0]), "+f"(c[1]), "+f"(c[2]), "+f"(c[3])
                 : "r"(a[0]), "r"(a[1]), "r"(a[2]), "r"(a[3]), "r"(b0), "r"(b1));
}
#define SWZ(o) ((o) ^ (((o) >> 3) & 0x70))

// f32x2 (packed fp32 FFMA2) for the GRU
__device__ __forceinline__ ull ffma2(ull a, ull b, ull c) {
    ull d; asm("fma.rn.f32x2 %0, %1, %2, %3;" : "=l"(d) : "l"(a), "l"(b), "l"(c)); return d;
}
union F2U { ull u; float2 f; };
__device__ __forceinline__ float hsum2(ull a) { F2U t; t.u = a; return t.f.x + t.f.y; }

// ---------------------------------------------------------------------------
// Kernel 0: split W_ih (both dirs) into bf16 hi/lo, K padded to 320.
// ---------------------------------------------------------------------------
__global__ void __launch_bounds__(256)
wsplit_kernel(const float* __restrict__ Wf, const float* __restrict__ Wb)
{
    int i = blockIdx.x * 256 + threadIdx.x;
    if (i >= NTOT * KP) return;
    const int n = i / KP, k = i % KP;
    float v = 0.f;
    if (k < II) v = (n < G3) ? Wf[(size_t)n * II + k] : Wb[(size_t)(n - G3) * II + k];
    __nv_bfloat16 hi = __float2bfloat16(v);
    float lo = v - __bfloat162float(hi);
    g_Whi[i] = hi;
    g_Wlo[i] = __float2bfloat16(lo);
}

// ---------------------------------------------------------------------------
// Kernel 1: proj GEMM, mma.sync bf16 3-pass split, x split FUSED in-kernel.
// CTA tile 128(M) x 128(N), 8 warps 2x4, K-chunk 64, 2-stage cp.async.
// Per chunk: cp.async raw fp32 x (zero-padded past K=300) + pre-split W bf16;
// convert x -> bf16 hi/lo A tiles in smem; then ldmatrix + mma.
// Grid (3 N fastest, 1024 M) for L2 A reuse.
// Smem: XF 2x32K | A hi+lo 32K | B 2x(hi16K+lo16K) = 160K -> 1 CTA/SM.
// ---------------------------------------------------------------------------
#define OFF_XF   0                    // 2 stages x 32768
#define OFF_AHI  65536
#define OFF_ALO  81920
#define OFF_B    98304                // stage s at +s*32768: hi +0, lo +16384
#define PROJ_SMEM (163840 + 1024)

__global__ void __launch_bounds__(256, 1)
proj_kernel(const float* __restrict__ x,
            const float* __restrict__ bf_, const float* __restrict__ bb_)
{
    extern __shared__ char dyn_smem[];
    const u32 base = (smem_u32(dyn_smem) + 1023u) & ~1023u;
    char* smem = dyn_smem + (base - smem_u32(dyn_smem));

    const int tid    = threadIdx.x;
    const int lane   = tid & 31;
    const int wid    = tid >> 5;
    const int warp_m = wid & 1;
    const int warp_n = wid >> 1;
    const int r0     = blockIdx.y * 128; // M tile
    const int n0     = blockIdx.x * 128; // N tile (fastest -> L2 A reuse)

    float acc[4][4][4];
    #pragma unroll
    for (int i = 0; i < 4; i++)
        #pragma unroll
        for (int j = 0; j < 4; j++)
            #pragma unroll
            for (int q = 0; q < 4; q++) acc[i][j][q] = 0.f;

    // ---- stage loader: x fp32 (2048x16B) + W hi/lo (2x1024x16B) ----
    auto load_stage = [&](int stg, int c) {
        const int k0 = c * 64;
        const u32 xf = base + OFF_XF + stg * 32768;
        const u32 bb = base + OFF_B  + stg * 32768;
        #pragma unroll
        for (int it = 0; it < 8; it++) {          // x: 2048 tasks
            const int t = tid + it * 256;
            const int row = t >> 4, q = t & 15;
            const bool valid = (k0 + q * 4) < II;  // 16B chunks align with 300
            const float* src = x + (size_t)(r0 + row) * II + (valid ? k0 + q * 4 : 0);
            cp16z(xf + (u32)(row * 256 + q * 16), src, valid);
        }
        #pragma unroll
        for (int it = 0; it < 4; it++) {          // W: 1024 tasks each hi/lo
            const int t = tid + it * 256;
            const int row = t >> 3, go = t & 7;
            const size_t wsrc = (size_t)(n0 + row) * KP + k0 + go * 8;
            const u32 off = SWZ((u32)(row * 128 + go * 16));
            cp16(bb + off,         g_Whi + wsrc);
            cp16(bb + 16384 + off, g_Wlo + wsrc);
        }
    };

    load_stage(0, 0);
    CP_COMMIT();

    const int lr  = lane & 7;
    const int mi4 = lane >> 3;

    for (int c = 0; c < 5; c++) {
        if (c + 1 < 5) { load_stage((c + 1) & 1, c + 1); CP_COMMIT(); CP_WAIT(1); }
        else           { CP_WAIT(0); }
        __syncthreads();   // XF/B stage ready; all warps past previous mma

        const int st = c & 1;
        // ---- convert x fp32 -> bf16 hi/lo A tiles (1024 tasks) ----
        {
            const char* xf = smem + OFF_XF + st * 32768;
            #pragma unroll
            for (int it = 0; it < 4; it++) {
                const int t = tid + it * 256;
                const int row = t >> 3, go = t & 7;
                float4 v0 = *(const float4*)(xf + row * 256 + go * 32);
                float4 v1 = *(const float4*)(xf + row * 256 + go * 32 + 16);
                float a[8] = {v0.x, v0.y, v0.z, v0.w, v1.x, v1.y, v1.z, v1.w};
                u32 hi[4], lo[4];
                #pragma unroll
                for (int q = 0; q < 4; q++) {
                    __nv_bfloat162 h2 = __floats2bfloat162_rn(a[2*q], a[2*q+1]);
                    float l0 = a[2*q]   - __bfloat162float(h2.x);
                    float l1 = a[2*q+1] - __bfloat162float(h2.y);
                    __nv_bfloat162 l2 = __floats2bfloat162_rn(l0, l1);
                    hi[q] = *(u32*)&h2;
                    lo[q] = *(u32*)&l2;
                }
                const u32 off = SWZ((u32)(row * 128 + go * 16));
                *(uint4*)(smem + OFF_AHI + off) = make_uint4(hi[0], hi[1], hi[2], hi[3]);
                *(uint4*)(smem + OFF_ALO + off) = make_uint4(lo[0], lo[1], lo[2], lo[3]);
            }
        }
        __syncthreads();   // A tiles ready

        const u32 sbB = base + OFF_B + st * 32768;

        #pragma unroll
        for (int kk = 0; kk < 4; kk++) {
            const int kb = kk * 32 + (mi4 >> 1) * 16;

            u32 ah[4][4], al[4][4], bh[2][4], bl[2][4];
            #pragma unroll
            for (int mi = 0; mi < 4; mi++) {
                const int row = warp_m * 64 + mi * 16 + (mi4 & 1) * 8 + lr;
                const u32 off = SWZ((u32)(row * 128 + kb));
                ldm4(ah[mi], base + OFF_AHI + off);
                ldm4(al[mi], base + OFF_ALO + off);
            }
            #pragma unroll
            for (int g = 0; g < 2; g++) {
                const int row = warp_n * 32 + g * 16 + (mi4 & 1) * 8 + lr;
                const u32 off = SWZ((u32)(row * 128 + kb));
                ldm4(bh[g], sbB + off);
                ldm4(bl[g], sbB + 16384 + off);
            }
            #pragma unroll
            for (int mi = 0; mi < 4; mi++)
                #pragma unroll
                for (int j = 0; j < 4; j++) {
                    const int g = j >> 1, sel = j & 1;
                    mma_bf16(acc[mi][j], ah[mi], bh[g][sel], bh[g][sel + 2]);
                    mma_bf16(acc[mi][j], ah[mi], bl[g][sel], bl[g][sel + 2]);
                    mma_bf16(acc[mi][j], al[mi], bh[g][sel], bh[g][sel + 2]);
                }
        }
        // next iteration's first __syncthreads protects A/B reuse
    }

    // ---- epilogue: bias + scatter to g_xp in scan order ----
    #pragma unroll
    for (int j = 0; j < 4; j++) {
        const int col = n0 + warp_n * 32 + j * 8 + (lane & 3) * 2;
        const int dir = (col >= G3) ? 1 : 0;
        const int g   = col - dir * G3;
        const float2 bv = *(const float2*)((dir ? bb_ : bf_) + g);
        #pragma unroll
        for (int mi = 0; mi < 4; mi++) {
            #pragma unroll
            for (int h = 0; h < 2; h++) {
                const int r = r0 + warp_m * 64 + mi * 16 + (lane >> 2) + h * 8;
                const int b = r >> 9, t = r & 511;
                const int s = dir ? (TT - 1 - t) : t;
                float2 o;
                o.x = acc[mi][j][2*h]   + bv.x;
                o.y = acc[mi][j][2*h+1] + bv.y;
                *(float2*)&g_xp[(((size_t)dir * TT + s) * BB + b) * G3 + g] = o;
            }
        }
    }
}

// ---------------------------------------------------------------------------
// Kernel 2: GRU recurrence (unchanged from R7 — proven at 323us).
// ---------------------------------------------------------------------------
__device__ __forceinline__ float sigmoid_fast(float a) {
    return 1.f / (1.f + __expf(-a));
}
__device__ __forceinline__ float tanh_fast(float a) {
    float c = fminf(fmaxf(a, -20.f), 20.f);
    float e = __expf(2.f * c);
    return (e - 1.f) / (e + 1.f);
}

__global__ void __launch_bounds__(128, 4)
gru_kernel(const float* __restrict__ Whh_f, const float* __restrict__ bhh_f,
           const float* __restrict__ Whh_b, const float* __restrict__ bhh_b)
{
    __shared__ __align__(16) float sh_h[2][64];
    __shared__ __align__(16) float ring[RING_D][192];

    const int tid  = threadIdx.x;
    const int j    = tid >> 1;
    const int half = tid & 1;
    const int dir  = blockIdx.x >> 8;
    const int b    = blockIdx.x & 255;

    const float* W  = dir ? Whh_b : Whh_f;
    const float* bh = dir ? bhh_b : bhh_f;

    ull wr[16], wz[16], wn[16];
    {
        const ulonglong2* Rr = (const ulonglong2*)(W + (size_t)j * 64         + half * 32);
        const ulonglong2* Rz = (const ulonglong2*)(W + (size_t)(j + 64) * 64  + half * 32);
        const ulonglong2* Rn = (const ulonglong2*)(W + (size_t)(j + 128) * 64 + half * 32);
        #pragma unroll
        for (int q = 0; q < 8; q++) {
            ((ulonglong2*)wr)[q] = Rr[q];
            ((ulonglong2*)wz)[q] = Rz[q];
            ((ulonglong2*)wn)[q] = Rn[q];
        }
    }
    const float br = bh[j], bz = bh[j + 64], bn = bh[j + 128];

    if (tid < 64) sh_h[0][tid] = 0.f;
    float h_old = 0.f;

    const float* xp_b = g_xp + ((size_t)dir * TT * BB + b) * G3;
    const size_t stride = (size_t)BB * G3;
    const u32 ring_base = smem_u32(ring);

    #pragma unroll
    for (int d = 0; d < RING_D; d++) {
        if (tid < 48)
            cp16(ring_base + (u32)(d * 768 + tid * 16),
                 xp_b + (size_t)d * stride + tid * 4);
        CP_COMMIT();
    }
    CP_WAIT(RING_D - 1);
    __syncthreads();

    #pragma unroll 1
    for (int s = 0; s < TT; s++) {
        const int slot = s & (RING_D - 1);
        const float* xp = ring[slot];
        const float xr = xp[j];
        const float xz = xp[j + 64];
        const float xn = xp[j + 128];

        const int pp = s & 1;
        const ulonglong2* hp = (const ulonglong2*)&sh_h[pp][half * 32];
        ull ar = 0ull, az = 0ull, an = 0ull;
        #pragma unroll
        for (int q = 0; q < 8; q++) {
            ulonglong2 h2 = hp[q];
            ar = ffma2(wr[2*q],   h2.x, ar);
            az = ffma2(wz[2*q],   h2.x, az);
            an = ffma2(wn[2*q],   h2.x, an);
            ar = ffma2(wr[2*q+1], h2.y, ar);
            az = ffma2(wz[2*q+1], h2.y, az);
            an = ffma2(wn[2*q+1], h2.y, an);
        }
        float gr = hsum2(ar), gz = hsum2(az), gn = hsum2(an);
        gr += __shfl_xor_sync(0xffffffffu, gr, 1);
        gz += __shfl_xor_sync(0xffffffffu, gz, 1);
        gn += __shfl_xor_sync(0xffffffffu, gn, 1);
        gr += br; gz += bz; gn += bn;

        const float r = sigmoid_fast(xr + gr);
        const float z = sigmoid_fast(xz + gz);
        const float n = tanh_fast(xn + r * gn);
        const float hnew = (1.f - z) * n + z * h_old;
        h_old = hnew;

        if (half == 0) {
            sh_h[1 - pp][j] = hnew;
            if (s == 0)
                g_feat[b * 256 + (dir ? 192 : 0) + j] = hnew;
        }

        CP_WAIT(RING_D - 2);
        __syncthreads();

        if (tid < 48)
            cp16(ring_base + (u32)(slot * 768 + tid * 16),
                 xp_b + (size_t)((s + RING_D) & (TT - 1)) * stride + tid * 4);
        CP_COMMIT();
    }

    if (half == 0)
        g_feat[b * 256 + (dir ? 64 : 128) + j] = h_old;
}

// ---------------------------------------------------------------------------
// Kernel 3: head. One warp per batch row.
// ---------------------------------------------------------------------------
__global__ void __launch_bounds__(32)
head_kernel(const float* __restrict__ W1, const float* __restrict__ b1,
            const float* __restrict__ W2, const float* __restrict__ b2,
            float* __restrict__ out)
{
    const int b = blockIdx.x;
    const int j = threadIdx.x;
    const float* f = g_feat + b * 256;
    const float* w = W1 + (size_t)j * 256;

    float acc = b1[j];
    #pragma unroll 8
    for (int k = 0; k < 256; k += 4) {
        float4 fv = *(const float4*)(f + k);
        float4 wv = *(const float4*)(w + k);
        acc += fv.x * wv.x + fv.y * wv.y + fv.z * wv.z + fv.w * wv.w;
    }
    acc = (acc >= 0.f) ? acc : 0.01f * acc;
    float v = acc * W2[j];
    #pragma unroll
    for (int off = 16; off; off >>= 1)
        v += __shfl_down_sync(0xffffffffu, v, off);
    if (j == 0) out[b] = v + b2[0];
}

// ---------------------------------------------------------------------------
extern "C" void kernel_launch(void* const* d_in, const int* in_sizes, int n_in,
                              void* d_out, int out_size)
{
    const float* x      = (const float*)d_in[0];
    const float* W_ih_f = (const float*)d_in[1];
    const float* W_hh_f = (const float*)d_in[2];
    const float* b_ih_f = (const float*)d_in[3];
    const float* b_hh_f = (const float*)d_in[4];
    const float* W_ih_b = (const float*)d_in[5];
    const float* W_hh_b = (const float*)d_in[6];
    const float* b_ih_b = (const float*)d_in[7];
    const float* b_hh_b = (const float*)d_in[8];
    const float* W1     = (const float*)d_in[9];
    const float* b1     = (const float*)d_in[10];
    const float* W2     = (const float*)d_in[11];
    const float* b2     = (const float*)d_in[12];
    float* out = (float*)d_out;

    cudaFuncSetAttribute(proj_kernel, cudaFuncAttributeMaxDynamicSharedMemorySize, PROJ_SMEM);

    wsplit_kernel<<<(NTOT * KP + 255) / 256, 256>>>(W_ih_f, W_ih_b);
    proj_kernel<<<dim3(3, 1024), 256, PROJ_SMEM>>>(x, b_ih_f, b_ih_b);
    gru_kernel<<<512, 128>>>(W_hh_f, b_hh_f, W_hh_b, b_hh_b);
    head_kernel<<<256, 32>>>(W1, b1, W2, b2, out);
}

// round 10
// speedup vs baseline: 1.0160x; 1.0160x over previous
#include <cuda_runtime.h>
#include <cuda_bf16.h>
#include <cstdint>

#define BB   256
#define TT   512
#define II   300
#define HH   64
#define G3   192
#define KP   320      // K padded: 5 chunks of 64
#define NTOT 384      // 192 fwd gates | 192 bwd gates
#define MTOT (BB * TT)
#define RING_D 16     // gru xp prefetch depth (steps)

typedef unsigned long long ull;
typedef uint32_t u32;

__device__ float g_xp[2ull * TT * BB * G3];          // 201 MB scratch
__device__ float g_feat[BB * 256];
__device__ __nv_bfloat16 g_Whi[NTOT * KP];
__device__ __nv_bfloat16 g_Wlo[NTOT * KP];
__device__ __nv_bfloat16 g_xhi[(size_t)MTOT * KP];   // 80 MB
__device__ __nv_bfloat16 g_xlo[(size_t)MTOT * KP];   // 80 MB

// ---------------------------------------------------------------------------
// Helpers (plain sm_80+ features — valid on compute_103)
// ---------------------------------------------------------------------------
__device__ __forceinline__ u32 smem_u32(const void* p) {
    u32 a;
    asm("{ .reg .u64 t; cvta.to.shared.u64 t, %1; cvt.u32.u64 %0, t; }" : "=r"(a) : "l"(p));
    return a;
}
__device__ __forceinline__ void cp16(u32 dst, const void* src) {
    asm volatile("cp.async.cg.shared.global [%0], [%1], 16;" :: "r"(dst), "l"(src));
}
#define CP_COMMIT()  asm volatile("cp.async.commit_group;" ::: "memory")
#define CP_WAIT(n)   asm volatile("cp.async.wait_group %0;" :: "n"(n) : "memory")

__device__ __forceinline__ void ldm4(u32* r, u32 addr) {
    asm volatile("ldmatrix.sync.aligned.m8n8.x4.shared.b16 {%0,%1,%2,%3}, [%4];"
                 : "=r"(r[0]), "=r"(r[1]), "=r"(r[2]), "=r"(r[3]) : "r"(addr));
}
__device__ __forceinline__ void mma_bf16(float* c, const u32* a, u32 b0, u32 b1) {
    asm volatile("mma.sync.aligned.m16n8k16.row.col.f32.bf16.bf16.f32 "
                 "{%0,%1,%2,%3}, {%4,%5,%6,%7}, {%8,%9}, {%0,%1,%2,%3};"
                 : "+f"(c[0]), "+f"(c[1]), "+f"(c[2]), "+f"(c[3])
                 : "r"(a[0]), "r"(a[1]), "r"(a[2]), "r"(a[3]), "r"(b0), "r"(b1));
}
#define SWZ(o) ((o) ^ (((o) >> 3) & 0x70))

// f32x2 (packed fp32 FFMA2) for the GRU
__device__ __forceinline__ ull ffma2(ull a, ull b, ull c) {
    ull d; asm("fma.rn.f32x2 %0, %1, %2, %3;" : "=l"(d) : "l"(a), "l"(b), "l"(c)); return d;
}
union F2U { ull u; float2 f; };
__device__ __forceinline__ float hsum2(ull a) { F2U t; t.u = a; return t.f.x + t.f.y; }

// ---------------------------------------------------------------------------
// Kernel 0a: split W_ih (both dirs) into bf16 hi/lo, K padded to 320.
// ---------------------------------------------------------------------------
__global__ void __launch_bounds__(256)
wsplit_kernel(const float* __restrict__ Wf, const float* __restrict__ Wb)
{
    int i = blockIdx.x * 256 + threadIdx.x;
    if (i >= NTOT * KP) return;
    const int n = i / KP, k = i % KP;
    float v = 0.f;
    if (k < II) v = (n < G3) ? Wf[(size_t)n * II + k] : Wb[(size_t)(n - G3) * II + k];
    __nv_bfloat16 hi = __float2bfloat16(v);
    float lo = v - __bfloat162float(hi);
    g_Whi[i] = hi;
    g_Wlo[i] = __float2bfloat16(lo);
}

// ---------------------------------------------------------------------------
// Kernel 0b: split x into bf16 hi/lo, K padded to 320. One thread = 8 cols.
// ---------------------------------------------------------------------------
__global__ void __launch_bounds__(256)
xsplit_kernel(const float* __restrict__ x)
{
    const int task = blockIdx.x * 256 + threadIdx.x;   // MTOT*40 tasks
    if (task >= MTOT * 40) return;
    const int row = task / 40;
    const int c0  = (task % 40) * 8;

    float a[8];
    const float* src = x + (size_t)row * II + c0;
    float4 v0 = make_float4(0.f, 0.f, 0.f, 0.f), v1 = v0;
    if (c0     <= 296) v0 = *(const float4*)src;
    if (c0 + 4 <= 296) v1 = *(const float4*)(src + 4);
    a[0]=v0.x; a[1]=v0.y; a[2]=v0.z; a[3]=v0.w;
    a[4]=v1.x; a[5]=v1.y; a[6]=v1.z; a[7]=v1.w;

    u32 hi[4], lo[4];
    #pragma unroll
    for (int q = 0; q < 4; q++) {
        __nv_bfloat162 h2 = __floats2bfloat162_rn(a[2*q], a[2*q+1]);
        float l0 = a[2*q]   - __bfloat162float(h2.x);
        float l1 = a[2*q+1] - __bfloat162float(h2.y);
        __nv_bfloat162 l2 = __floats2bfloat162_rn(l0, l1);
        hi[q] = *(u32*)&h2;
        lo[q] = *(u32*)&l2;
    }
    const size_t di = (size_t)row * KP + c0;
    *(uint4*)(g_xhi + di) = make_uint4(hi[0], hi[1], hi[2], hi[3]);
    *(uint4*)(g_xlo + di) = make_uint4(lo[0], lo[1], lo[2], lo[3]);
}

// ---------------------------------------------------------------------------
// Kernel 1: proj GEMM via mma.sync bf16, 3-pass split (hi*hi + hi*lo + lo*hi).
// CTA tile 128(M) x 128(N), 8 warps 2x4 (warp tile 64x32), K-chunk 64,
// THREE-stage cp.async pipeline: loads for chunk c+2 overlap compute of c.
// Grid (3 N fastest, 1024 M) -> A served from L2 for 2 of 3 N-tiles.
// ---------------------------------------------------------------------------
#define STG_BYTES 65536          // 4 tiles x 16 KB
#define OFF_AHI 0
#define OFF_ALO 16384
#define OFF_BHI 32768
#define OFF_BLO 49152
#define PROJ_SMEM (3 * STG_BYTES + 1024)

__global__ void __launch_bounds__(256, 1)
proj_kernel(const float* __restrict__ bf_, const float* __restrict__ bb_)
{
    extern __shared__ char dyn_smem[];
    const u32 base = (smem_u32(dyn_smem) + 1023u) & ~1023u;

    const int tid    = threadIdx.x;
    const int lane   = tid & 31;
    const int wid    = tid >> 5;
    const int warp_m = wid & 1;
    const int warp_n = wid >> 1;
    const int r0     = blockIdx.y * 128; // M tile
    const int n0     = blockIdx.x * 128; // N tile (fastest -> L2 A reuse)

    float acc[4][4][4];
    #pragma unroll
    for (int i = 0; i < 4; i++)
        #pragma unroll
        for (int j = 0; j < 4; j++)
            #pragma unroll
            for (int q = 0; q < 4; q++) acc[i][j][q] = 0.f;

    auto load_stage = [&](int stg, int c) {
        const int k0 = c * 64;
        const u32 sb = base + stg * STG_BYTES;
        #pragma unroll
        for (int it = 0; it < 4; it++) {
            const int t = tid + it * 256;
            const int row = t >> 3, q = t & 7;
            const u32 off = SWZ((u32)(row * 128 + q * 16));
            const size_t asrc = (size_t)(r0 + row) * KP + k0 + q * 8;
            const size_t bsrc = (size_t)(n0 + row) * KP + k0 + q * 8;
            cp16(sb + OFF_AHI + off, g_xhi + asrc);
            cp16(sb + OFF_ALO + off, g_xlo + asrc);
            cp16(sb + OFF_BHI + off, g_Whi + bsrc);
            cp16(sb + OFF_BLO + off, g_Wlo + bsrc);
        }
    };

    // Prologue: stages for chunks 0 and 1 in flight.
    load_stage(0, 0); CP_COMMIT();
    load_stage(1, 1); CP_COMMIT();

    const int lr  = lane & 7;
    const int mi4 = lane >> 3;

    int stg = 0;
    for (int c = 0; c < 5; c++) {
        CP_WAIT(1);          // chunk c complete (c+1 may still be in flight)
        __syncthreads();     // and all warps done reading the stage we refill

        // Refill the just-freed stage with chunk c+2 (overlaps compute of c).
        if (c + 2 < 5) {
            load_stage((stg + 2) % 3, c + 2);
            CP_COMMIT();
        } else {
            CP_COMMIT();     // empty group keeps CP_WAIT(1) arithmetic uniform
        }

        const u32 sb = base + stg * STG_BYTES;

        #pragma unroll
        for (int kk = 0; kk < 4; kk++) {
            const int kb = kk * 32 + (mi4 >> 1) * 16;

            u32 ah[4][4], al[4][4], bh[2][4], bl[2][4];
            #pragma unroll
            for (int mi = 0; mi < 4; mi++) {
                const int row = warp_m * 64 + mi * 16 + (mi4 & 1) * 8 + lr;
                const u32 off = SWZ((u32)(row * 128 + kb));
                ldm4(ah[mi], sb + OFF_AHI + off);
                ldm4(al[mi], sb + OFF_ALO + off);
            }
            #pragma unroll
            for (int g = 0; g < 2; g++) {
                const int row = warp_n * 32 + g * 16 + (mi4 & 1) * 8 + lr;
                const u32 off = SWZ((u32)(row * 128 + kb));
                ldm4(bh[g], sb + OFF_BHI + off);
                ldm4(bl[g], sb + OFF_BLO + off);
            }
            #pragma unroll
            for (int mi = 0; mi < 4; mi++)
                #pragma unroll
                for (int j = 0; j < 4; j++) {
                    const int g = j >> 1, sel = j & 1;
                    mma_bf16(acc[mi][j], ah[mi], bh[g][sel], bh[g][sel + 2]);
                    mma_bf16(acc[mi][j], ah[mi], bl[g][sel], bl[g][sel + 2]);
                    mma_bf16(acc[mi][j], al[mi], bh[g][sel], bh[g][sel + 2]);
                }
        }
        stg = (stg + 1) % 3;
    }

    // ---- epilogue: bias + scatter to g_xp in scan order ----
    #pragma unroll
    for (int j = 0; j < 4; j++) {
        const int col = n0 + warp_n * 32 + j * 8 + (lane & 3) * 2;
        const int dir = (col >= G3) ? 1 : 0;
        const int g   = col - dir * G3;
        const float2 bv = *(const float2*)((dir ? bb_ : bf_) + g);
        #pragma unroll
        for (int mi = 0; mi < 4; mi++) {
            #pragma unroll
            for (int h = 0; h < 2; h++) {
                const int r = r0 + warp_m * 64 + mi * 16 + (lane >> 2) + h * 8;
                const int b = r >> 9, t = r & 511;
                const int s = dir ? (TT - 1 - t) : t;
                float2 o;
                o.x = acc[mi][j][2*h]   + bv.x;
                o.y = acc[mi][j][2*h+1] + bv.y;
                *(float2*)&g_xp[(((size_t)dir * TT + s) * BB + b) * G3 + g] = o;
            }
        }
    }
}

// ---------------------------------------------------------------------------
// Kernel 2: GRU recurrence, pair-split + cp.async xp ring (depth 16).
// ---------------------------------------------------------------------------
__device__ __forceinline__ float sigmoid_fast(float a) {
    return 1.f / (1.f + __expf(-a));
}
__device__ __forceinline__ float tanh_fast(float a) {
    float c = fminf(fmaxf(a, -20.f), 20.f);
    float e = __expf(2.f * c);
    return (e - 1.f) / (e + 1.f);
}

__global__ void __launch_bounds__(128, 4)
gru_kernel(const float* __restrict__ Whh_f, const float* __restrict__ bhh_f,
           const float* __restrict__ Whh_b, const float* __restrict__ bhh_b)
{
    __shared__ __align__(16) float sh_h[2][64];
    __shared__ __align__(16) float ring[RING_D][192];

    const int tid  = threadIdx.x;
    const int j    = tid >> 1;
    const int half = tid & 1;
    const int dir  = blockIdx.x >> 8;
    const int b    = blockIdx.x & 255;

    const float* W  = dir ? Whh_b : Whh_f;
    const float* bh = dir ? bhh_b : bhh_f;

    ull wr[16], wz[16], wn[16];
    {
        const ulonglong2* Rr = (const ulonglong2*)(W + (size_t)j * 64         + half * 32);
        const ulonglong2* Rz = (const ulonglong2*)(W + (size_t)(j + 64) * 64  + half * 32);
        const ulonglong2* Rn = (const ulonglong2*)(W + (size_t)(j + 128) * 64 + half * 32);
        #pragma unroll
        for (int q = 0; q < 8; q++) {
            ((ulonglong2*)wr)[q] = Rr[q];
            ((ulonglong2*)wz)[q] = Rz[q];
            ((ulonglong2*)wn)[q] = Rn[q];
        }
    }
    const float br = bh[j], bz = bh[j + 64], bn = bh[j + 128];

    if (tid < 64) sh_h[0][tid] = 0.f;
    float h_old = 0.f;

    const float* xp_b = g_xp + ((size_t)dir * TT * BB + b) * G3;
    const size_t stride = (size_t)BB * G3;
    const u32 ring_base = smem_u32(ring);

    #pragma unroll
    for (int d = 0; d < RING_D; d++) {
        if (tid < 48)
            cp16(ring_base + (u32)(d * 768 + tid * 16),
                 xp_b + (size_t)d * stride + tid * 4);
        CP_COMMIT();
    }
    CP_WAIT(RING_D - 1);
    __syncthreads();

    #pragma unroll 2
    for (int s = 0; s < TT; s++) {
        const int slot = s & (RING_D - 1);
        const float* xp = ring[slot];
        const float xr = xp[j];
        const float xz = xp[j + 64];
        const float xn = xp[j + 128];

        const int pp = s & 1;
        const ulonglong2* hp = (const ulonglong2*)&sh_h[pp][half * 32];
        ull ar = 0ull, az = 0ull, an = 0ull;
        #pragma unroll
        for (int q = 0; q < 8; q++) {
            ulonglong2 h2 = hp[q];
            ar = ffma2(wr[2*q],   h2.x, ar);
            az = ffma2(wz[2*q],   h2.x, az);
            an = ffma2(wn[2*q],   h2.x, an);
            ar = ffma2(wr[2*q+1], h2.y, ar);
            az = ffma2(wz[2*q+1], h2.y, az);
            an = ffma2(wn[2*q+1], h2.y, an);
        }
        float gr = hsum2(ar), gz = hsum2(az), gn = hsum2(an);
        gr += __shfl_xor_sync(0xffffffffu, gr, 1);
        gz += __shfl_xor_sync(0xffffffffu, gz, 1);
        gn += __shfl_xor_sync(0xffffffffu, gn, 1);
        gr += br; gz += bz; gn += bn;

        const float r = sigmoid_fast(xr + gr);
        const float z = sigmoid_fast(xz + gz);
        const float n = tanh_fast(xn + r * gn);
        const float hnew = (1.f - z) * n + z * h_old;
        h_old = hnew;

        if (half == 0) {
            sh_h[1 - pp][j] = hnew;
            if (s == 0)
                g_feat[b * 256 + (dir ? 192 : 0) + j] = hnew;
        }

        CP_WAIT(RING_D - 2);
        __syncthreads();

        if (tid < 48)
            cp16(ring_base + (u32)(slot * 768 + tid * 16),
                 xp_b + (size_t)((s + RING_D) & (TT - 1)) * stride + tid * 4);
        CP_COMMIT();
    }

    if (half == 0)
        g_feat[b * 256 + (dir ? 64 : 128) + j] = h_old;
}

// ---------------------------------------------------------------------------
// Kernel 3: head. 8 warps per block, one warp per batch row; 32 blocks.
// ---------------------------------------------------------------------------
__global__ void __launch_bounds__(256)
head_kernel(const float* __restrict__ W1, const float* __restrict__ b1,
            const float* __restrict__ W2, const float* __restrict__ b2,
            float* __restrict__ out)
{
    const int wid = threadIdx.x >> 5;
    const int j   = threadIdx.x & 31;
    const int b   = blockIdx.x * 8 + wid;
    const float* f = g_feat + b * 256;
    const float* w = W1 + (size_t)j * 256;

    float acc = b1[j];
    #pragma unroll 8
    for (int k = 0; k < 256; k += 4) {
        float4 fv = *(const float4*)(f + k);
        float4 wv = *(const float4*)(w + k);
        acc += fv.x * wv.x + fv.y * wv.y + fv.z * wv.z + fv.w * wv.w;
    }
    acc = (acc >= 0.f) ? acc : 0.01f * acc;
    float v = acc * W2[j];
    #pragma unroll
    for (int off = 16; off; off >>= 1)
        v += __shfl_down_sync(0xffffffffu, v, off);
    if (j == 0) out[b] = v + b2[0];
}

// ---------------------------------------------------------------------------
extern "C" void kernel_launch(void* const* d_in, const int* in_sizes, int n_in,
                              void* d_out, int out_size)
{
    const float* x      = (const float*)d_in[0];
    const float* W_ih_f = (const float*)d_in[1];
    const float* W_hh_f = (const float*)d_in[2];
    const float* b_ih_f = (const float*)d_in[3];
    const float* b_hh_f = (const float*)d_in[4];
    const float* W_ih_b = (const float*)d_in[5];
    const float* W_hh_b = (const float*)d_in[6];
    const float* b_ih_b = (const float*)d_in[7];
    const float* b_hh_b = (const float*)d_in[8];
    const float* W1     = (const float*)d_in[9];
    const float* b1     = (const float*)d_in[10];
    const float* W2     = (const float*)d_in[11];
    const float* b2     = (const float*)d_in[12];
    float* out = (float*)d_out;

    cudaFuncSetAttribute(proj_kernel, cudaFuncAttributeMaxDynamicSharedMemorySize, PROJ_SMEM);

    wsplit_kernel<<<(NTOT * KP + 255) / 256, 256>>>(W_ih_f, W_ih_b);
    xsplit_kernel<<<(MTOT * 40 + 255) / 256, 256>>>(x);
    proj_kernel<<<dim3(3, 1024), 256, PROJ_SMEM>>>(b_ih_f, b_ih_b);
    gru_kernel<<<512, 128>>>(W_hh_f, b_hh_f, W_hh_b, b_hh_b);
    head_kernel<<<32, 256>>>(W1, b1, W2, b2, out);
}